// round 13
// baseline (speedup 1.0000x reference)
#include <cuda_runtime.h>
#include <math.h>

#define S 16384
#define I 64
#define R 2048
#define H 128
#define O 50
#define NB 128          // persistent scan CTAs, one wave
#define NT 512          // 16 warps
#define RPC 16          // rows per CTA = R / NB

__device__ float g_states[(size_t)S * R];   // h_t for all t (exchange + out_kernel input)
__device__ float g_xinT[(size_t)R * S];     // x @ Win.T, TRANSPOSED [r][t]
__device__ float g_wcombT[R * O];           // fused fc2@fc1, TRANSPOSED [r][o]
__device__ float g_bcomb[O];
__device__ __align__(32) unsigned g_flags[NB];  // per-CTA step flags (monotonic)

// ---- packed dual-fp32 helpers -------------------------------------------
__device__ __forceinline__ void ffma2(unsigned long long &d,
                                      unsigned long long a,
                                      unsigned long long b) {
    asm("fma.rn.f32x2 %0, %1, %2, %0;" : "+l"(d) : "l"(a), "l"(b));
}
__device__ __forceinline__ unsigned long long pack2(float a, float b) {
    unsigned long long r;
    asm("mov.b64 %0, {%1, %2};" : "=l"(r) : "f"(a), "f"(b));
    return r;
}
__device__ __forceinline__ float f2lo(unsigned long long v) {
    return __uint_as_float((unsigned)v);
}
__device__ __forceinline__ float f2hi(unsigned long long v) {
    return __uint_as_float((unsigned)(v >> 32));
}

// ---------------------------------------------------------------------------
// Kernel 1: W_combT[r][o] = sum_h fc2_w[o][h]*fc1_w[h][r]; b_comb; reset flags
//   grid (O, 8): each block does 256 r values for one o.
// ---------------------------------------------------------------------------
__global__ void wcomb_kernel(const float* __restrict__ fc1_w,
                             const float* __restrict__ fc1_b,
                             const float* __restrict__ fc2_w,
                             const float* __restrict__ fc2_b) {
    const int o = blockIdx.x;
    const int r = blockIdx.y * 256 + threadIdx.x;
    __shared__ float w2[H];
    if (threadIdx.x < H) w2[threadIdx.x] = fc2_w[o * H + threadIdx.x];
    __syncthreads();
    float acc = 0.f;
#pragma unroll 8
    for (int h = 0; h < H; h++) acc += w2[h] * fc1_w[(size_t)h * R + r];
    g_wcombT[(size_t)r * O + o] = acc;
    if (blockIdx.y == 0 && threadIdx.x == 0) {
        float b = fc2_b[o];
        for (int h = 0; h < H; h++) b += w2[h] * fc1_b[h];
        g_bcomb[o] = b;
    }
    if (o == 0 && blockIdx.y == 0 && threadIdx.x < NB)
        g_flags[threadIdx.x] = 0u;      // stream-ordered reset before the scan
}

// ---------------------------------------------------------------------------
// Kernel 1b: xinT[r][t] = x[t,:] . Win[r,:]   (tiled 64t x 128r, smem transpose)
// ---------------------------------------------------------------------------
#define XT 64
#define XR 128
__global__ void __launch_bounds__(256)
xin_kernel(const float* __restrict__ x, const float* __restrict__ Win) {
    __shared__ float xs[XT * I];        // [t][k]  16 KB
    __shared__ float wst[I * XR];       // [k][r]  32 KB (transposed)
    __shared__ float ot[XR * XT];       // [r][t]  32 KB (output transpose stage)
    const int tid = threadIdx.x;
    const int t0 = blockIdx.x * XT;
    const int r0 = blockIdx.y * XR;

    for (int f = tid; f < XT * I / 4; f += 256)
        *reinterpret_cast<float4*>(&xs[4 * f]) =
            *reinterpret_cast<const float4*>(x + (size_t)t0 * I + 4 * f);
    for (int f = tid; f < XR * I / 4; f += 256) {
        const int r = f >> 4;
        const int k4 = (f & 15) * 4;
        const float4 v = *reinterpret_cast<const float4*>(
            Win + (size_t)(r0 + r) * I + k4);
        wst[(k4 + 0) * XR + r] = v.x;
        wst[(k4 + 1) * XR + r] = v.y;
        wst[(k4 + 2) * XR + r] = v.z;
        wst[(k4 + 3) * XR + r] = v.w;
    }
    __syncthreads();

    const int tr = tid & 15;        // r-group: 8 consecutive r
    const int tt = tid >> 4;        // t-group: 4 consecutive t
    float acc[4][8];
#pragma unroll
    for (int i = 0; i < 4; i++)
#pragma unroll
        for (int j = 0; j < 8; j++) acc[i][j] = 0.f;

    for (int k = 0; k < I; k++) {
        float b[8];
        const float4 b0 = *reinterpret_cast<const float4*>(&wst[k * XR + tr * 8]);
        const float4 b1 = *reinterpret_cast<const float4*>(&wst[k * XR + tr * 8 + 4]);
        b[0] = b0.x; b[1] = b0.y; b[2] = b0.z; b[3] = b0.w;
        b[4] = b1.x; b[5] = b1.y; b[6] = b1.z; b[7] = b1.w;
#pragma unroll
        for (int i = 0; i < 4; i++) {
            const float a = xs[(tt * 4 + i) * I + k];
#pragma unroll
            for (int j = 0; j < 8; j++) acc[i][j] += a * b[j];
        }
    }
    // stage through smem as [r][t], then coalesced f4 stores over t
#pragma unroll
    for (int i = 0; i < 4; i++)
#pragma unroll
        for (int j = 0; j < 8; j++)
            ot[(tr * 8 + j) * XT + (tt * 4 + i)] = acc[i][j];
    __syncthreads();
    for (int f = tid; f < XR * XT / 4; f += 256) {
        const int r = f >> 4;               // 16 float4 per row of 64 t
        const int t4 = (f & 15) * 4;
        *reinterpret_cast<float4*>(&g_xinT[(size_t)(r0 + r) * S + t0 + t4]) =
            *reinterpret_cast<const float4*>(&ot[r * XT + t4]);
    }
}

// ---------------------------------------------------------------------------
// Kernel 2: persistent scan, wavefront sync.
//   Warp w consumes h rows 128w..128w+127, produced by CTAs 8w..8w+7 only.
//   Each warp polls exactly those 8 per-CTA flags (one 32B sector, converged).
// ---------------------------------------------------------------------------
__global__ void __launch_bounds__(NT, 1)
scan_kernel(const float* __restrict__ W) {
    __shared__ float cross[RPC][17];     // [row][warp], padded

    const int tid  = threadIdx.x;
    const int warp = tid >> 5;
    const int lane = tid & 31;
    const int bid  = blockIdx.x;
    const int row  = RPC * bid + warp;   // this warp's output row
    const int colbase = 4 * tid;         // this thread's 4 h columns

    // W registers: 16 rows x 4 cols (coalesced one-time load)
    unsigned long long wlo[RPC], whi[RPC];
#pragma unroll
    for (int j = 0; j < RPC; j++) {
        const float4 wv = *reinterpret_cast<const float4*>(
            W + (size_t)(RPC * bid + j) * R + colbase);
        wlo[j] = pack2(wv.x, wv.y);
        whi[j] = pack2(wv.z, wv.w);
    }

    // the producer CTA of this thread's 4 h columns: 8*warp + lane/4
    const unsigned* myflag = &g_flags[8 * warp + (lane >> 2)];

    // xin chunks: lane l holds xinT[row][tc+l]
    const float* xrow = g_xinT + (size_t)row * S;
    float xcur = xrow[lane];             // chunk t = 0..31
    float xnxt = xrow[32 + lane];        // chunk t = 32..63

    float hprev = 0.f;                   // lane0 of warp w: h_prev of its row
    float4 h4 = make_float4(0.f, 0.f, 0.f, 0.f);

    for (int t = 0; t < S; t++) {
        if ((t & 31) == 0 && t) {
            xcur = xnxt;
            const int nb = t + 32;
            if (nb < S) xnxt = xrow[nb + lane];   // 32-step prefetch distance
        }
        const float xval = __shfl_sync(0xffffffffu, xcur, t & 31);

        // ---- partial dots: 16 rows over this thread's 4 h columns ----
        const unsigned long long hlo = pack2(h4.x, h4.y);
        const unsigned long long hhi = pack2(h4.z, h4.w);
        float p[RPC];
#pragma unroll
        for (int j = 0; j < RPC; j++) {
            unsigned long long acc = 0ull;
            ffma2(acc, wlo[j], hlo);
            ffma2(acc, whi[j], hhi);
            p[j] = f2lo(acc) + f2hi(acc);
        }

        // ---- in-warp multi-value butterfly: 32 lanes x 16 rows -> 16 sums ----
#pragma unroll
        for (int i = 0; i < 8; i++) {
            float sv = (lane & 16) ? p[i] : p[i + 8];
            float rv = __shfl_xor_sync(0xffffffffu, sv, 16);
            p[i] = ((lane & 16) ? p[i + 8] : p[i]) + rv;
        }
#pragma unroll
        for (int i = 0; i < 4; i++) {
            float sv = (lane & 8) ? p[i] : p[i + 4];
            float rv = __shfl_xor_sync(0xffffffffu, sv, 8);
            p[i] = ((lane & 8) ? p[i + 4] : p[i]) + rv;
        }
#pragma unroll
        for (int i = 0; i < 2; i++) {
            float sv = (lane & 4) ? p[i] : p[i + 2];
            float rv = __shfl_xor_sync(0xffffffffu, sv, 4);
            p[i] = ((lane & 4) ? p[i + 2] : p[i]) + rv;
        }
        {
            float sv = (lane & 2) ? p[0] : p[1];
            float rv = __shfl_xor_sync(0xffffffffu, sv, 2);
            p[0] = ((lane & 2) ? p[1] : p[0]) + rv;
        }
        p[0] += __shfl_xor_sync(0xffffffffu, p[0], 1);
        const int rowloc = ((lane >> 4) & 1) * 8 + ((lane >> 3) & 1) * 4 +
                           ((lane >> 2) & 1) * 2 + ((lane >> 1) & 1);
        if ((lane & 1) == 0) cross[rowloc][warp] = p[0];
        __syncthreads();

        // ---- final per-row reduce: warp w owns row RPC*bid + w ----
        float v = (lane < 16) ? cross[warp][lane] : 0.f;
        v += __shfl_xor_sync(0xffffffffu, v, 8);
        v += __shfl_xor_sync(0xffffffffu, v, 4);
        v += __shfl_xor_sync(0xffffffffu, v, 2);
        v += __shfl_xor_sync(0xffffffffu, v, 1);

        if (lane == 0) {
            v += xval;
            const float a = fabsf(v);
            const float e = __expf(-2.f * a);
            float th = __fdividef(1.f - e, 1.f + e);     // tanh(|v|)
            th = copysignf(th, v);
            const float hn = 0.5f * hprev + 0.5f * th;   // ALPHA = 0.5
            hprev = hn;
            g_states[(size_t)t * R + row] = hn;
        }
        if (t + 1 == S) break;

        __syncthreads();   // all 16 rows stored (and cross[] reads done)

        // ---- publish: this CTA finished step t ----
        if (tid == 0)
            asm volatile("st.release.gpu.global.u32 [%0], %1;"
                         :: "l"(&g_flags[bid]), "r"((unsigned)(t + 1)) : "memory");

        // ---- wavefront wait: poll ONLY this warp's 8 producer CTAs ----
        {
            unsigned vv;
            bool ok;
            do {
                asm volatile("ld.acquire.gpu.u32 %0, [%1];"
                             : "=r"(vv) : "l"(myflag) : "memory");
                ok = (vv > (unsigned)t);
            } while (!__all_sync(0xffffffffu, ok));
        }

        // ---- load own 4 h values (fresh cache lines, ordered by acquire) ----
        h4 = *reinterpret_cast<const float4*>(&g_states[(size_t)t * R + colbase]);
    }
}

// ---------------------------------------------------------------------------
// Kernel 3: out[t][o] = states[t,:] . W_comb[o,:] + b_comb[o]
// ---------------------------------------------------------------------------
#define OT 128
#define KC 64
__global__ void __launch_bounds__(OT)
out_kernel(float* __restrict__ out) {
    __shared__ float st_s[OT][KC + 1];                  // 33.3 KB
    __shared__ unsigned long long wcs[KC][O / 2];       // 12.8 KB
    const int tid = threadIdx.x;
    const int t0  = blockIdx.x * OT;

    unsigned long long acc[O / 2];
#pragma unroll
    for (int op = 0; op < O / 2; op++) acc[op] = 0ull;

    for (int kc = 0; kc < R; kc += KC) {
        __syncthreads();
#pragma unroll
        for (int i = 0; i < (OT * KC) / (4 * OT); i++) {
            const int f  = tid + OT * i;
            const int tt = f >> 4;
            const int k4 = (f & 15) * 4;
            const float4 vv = *reinterpret_cast<const float4*>(
                &g_states[(size_t)(t0 + tt) * R + kc + k4]);
            st_s[tt][k4 + 0] = vv.x; st_s[tt][k4 + 1] = vv.y;
            st_s[tt][k4 + 2] = vv.z; st_s[tt][k4 + 3] = vv.w;
        }
        for (int i = tid; i < KC * (O / 2); i += OT) {
            const int r = i / (O / 2), op = i - r * (O / 2);
            wcs[r][op] = *reinterpret_cast<const unsigned long long*>(
                &g_wcombT[(size_t)(kc + r) * O + 2 * op]);
        }
        __syncthreads();
#pragma unroll 4
        for (int kk = 0; kk < KC; kk++) {
            const float s = st_s[tid][kk];
            const unsigned long long ss = pack2(s, s);
#pragma unroll
            for (int op = 0; op < O / 2; op++) ffma2(acc[op], wcs[kk][op], ss);
        }
    }
#pragma unroll
    for (int op = 0; op < O / 2; op++) {
        out[(size_t)(t0 + tid) * O + 2 * op + 0] = f2lo(acc[op]) + g_bcomb[2 * op + 0];
        out[(size_t)(t0 + tid) * O + 2 * op + 1] = f2hi(acc[op]) + g_bcomb[2 * op + 1];
    }
}

// ---------------------------------------------------------------------------
extern "C" void kernel_launch(void* const* d_in, const int* in_sizes, int n_in,
                              void* d_out, int out_size) {
    const float* x     = (const float*)d_in[0];
    const float* Win   = (const float*)d_in[1];
    const float* W     = (const float*)d_in[2];
    const float* fc1_w = (const float*)d_in[3];
    const float* fc1_b = (const float*)d_in[4];
    const float* fc2_w = (const float*)d_in[5];
    const float* fc2_b = (const float*)d_in[6];
    float* out = (float*)d_out;

    wcomb_kernel<<<dim3(O, 8), 256>>>(fc1_w, fc1_b, fc2_w, fc2_b);  // resets g_flags
    xin_kernel<<<dim3(S / XT, R / XR), 256>>>(x, Win);
    scan_kernel<<<NB, NT>>>(W);
    out_kernel<<<S / OT, OT>>>(out);
}

// round 17
// speedup vs baseline: 4.9830x; 4.9830x over previous
#include <cuda_runtime.h>
#include <math.h>

#define S 16384
#define I 64
#define R 2048
#define H 128
#define O 50
#define NB 128          // persistent scan CTAs, one wave
#define NBH 64          // CTAs per half (producers of each col half)
#define NT 512          // 16 warps
#define RPC 16          // rows per CTA = R / NB

__device__ float g_states[(size_t)S * R];   // h_t for all t (exchange + out_kernel input)
__device__ float g_xinT[(size_t)R * S];     // x @ Win.T, TRANSPOSED [r][t]
__device__ float g_wcombT[R * O];           // fused fc2@fc1, TRANSPOSED [r][o]
__device__ float g_bcomb[O];
__device__ unsigned g_cnt[2];               // per-half arrival counters (monotonic)

// ---- packed dual-fp32 helpers (used in out_kernel) -----------------------
__device__ __forceinline__ void ffma2(unsigned long long &d,
                                      unsigned long long a,
                                      unsigned long long b) {
    asm("fma.rn.f32x2 %0, %1, %2, %0;" : "+l"(d) : "l"(a), "l"(b));
}
__device__ __forceinline__ unsigned long long pack2(float a, float b) {
    unsigned long long r;
    asm("mov.b64 %0, {%1, %2};" : "=l"(r) : "f"(a), "f"(b));
    return r;
}
__device__ __forceinline__ float f2lo(unsigned long long v) {
    return __uint_as_float((unsigned)v);
}
__device__ __forceinline__ float f2hi(unsigned long long v) {
    return __uint_as_float((unsigned)(v >> 32));
}

// ---------------------------------------------------------------------------
// Kernel 1: W_combT[r][o] = sum_h fc2_w[o][h]*fc1_w[h][r]; b_comb; reset cnts
// ---------------------------------------------------------------------------
__global__ void wcomb_kernel(const float* __restrict__ fc1_w,
                             const float* __restrict__ fc1_b,
                             const float* __restrict__ fc2_w,
                             const float* __restrict__ fc2_b) {
    const int o = blockIdx.x;
    const int r = blockIdx.y * 256 + threadIdx.x;
    __shared__ float w2[H];
    if (threadIdx.x < H) w2[threadIdx.x] = fc2_w[o * H + threadIdx.x];
    __syncthreads();
    float acc = 0.f;
#pragma unroll 8
    for (int h = 0; h < H; h++) acc += w2[h] * fc1_w[(size_t)h * R + r];
    g_wcombT[(size_t)r * O + o] = acc;
    if (blockIdx.y == 0 && threadIdx.x == 0) {
        float b = fc2_b[o];
        for (int h = 0; h < H; h++) b += w2[h] * fc1_b[h];
        g_bcomb[o] = b;
    }
    if (o == 0 && blockIdx.y == 0 && threadIdx.x < 2)
        g_cnt[threadIdx.x] = 0u;        // stream-ordered reset before the scan
}

// ---------------------------------------------------------------------------
// Kernel 1b: xinT[r][t] = x[t,:] . Win[r,:]   (tiled 64t x 128r, smem transpose)
// ---------------------------------------------------------------------------
#define XT 64
#define XR 128
__global__ void __launch_bounds__(256)
xin_kernel(const float* __restrict__ x, const float* __restrict__ Win) {
    __shared__ float xs[XT * I];        // [t][k]  16 KB
    __shared__ float wst[I * XR];       // [k][r]  32 KB (transposed)
    __shared__ float ot[XR * XT];       // [r][t]  32 KB (output transpose stage)
    const int tid = threadIdx.x;
    const int t0 = blockIdx.x * XT;
    const int r0 = blockIdx.y * XR;

    for (int f = tid; f < XT * I / 4; f += 256)
        *reinterpret_cast<float4*>(&xs[4 * f]) =
            *reinterpret_cast<const float4*>(x + (size_t)t0 * I + 4 * f);
    for (int f = tid; f < XR * I / 4; f += 256) {
        const int r = f >> 4;
        const int k4 = (f & 15) * 4;
        const float4 v = *reinterpret_cast<const float4*>(
            Win + (size_t)(r0 + r) * I + k4);
        wst[(k4 + 0) * XR + r] = v.x;
        wst[(k4 + 1) * XR + r] = v.y;
        wst[(k4 + 2) * XR + r] = v.z;
        wst[(k4 + 3) * XR + r] = v.w;
    }
    __syncthreads();

    const int tr = tid & 15;        // r-group: 8 consecutive r
    const int tt = tid >> 4;        // t-group: 4 consecutive t
    float acc[4][8];
#pragma unroll
    for (int i = 0; i < 4; i++)
#pragma unroll
        for (int j = 0; j < 8; j++) acc[i][j] = 0.f;

    for (int k = 0; k < I; k++) {
        float b[8];
        const float4 b0 = *reinterpret_cast<const float4*>(&wst[k * XR + tr * 8]);
        const float4 b1 = *reinterpret_cast<const float4*>(&wst[k * XR + tr * 8 + 4]);
        b[0] = b0.x; b[1] = b0.y; b[2] = b0.z; b[3] = b0.w;
        b[4] = b1.x; b[5] = b1.y; b[6] = b1.z; b[7] = b1.w;
#pragma unroll
        for (int i = 0; i < 4; i++) {
            const float a = xs[(tt * 4 + i) * I + k];
#pragma unroll
            for (int j = 0; j < 8; j++) acc[i][j] += a * b[j];
        }
    }
    // stage through smem as [r][t], then coalesced f4 stores over t
#pragma unroll
    for (int i = 0; i < 4; i++)
#pragma unroll
        for (int j = 0; j < 8; j++)
            ot[(tr * 8 + j) * XT + (tt * 4 + i)] = acc[i][j];
    __syncthreads();
    for (int f = tid; f < XR * XT / 4; f += 256) {
        const int r = f >> 4;               // 16 float4 per row of 64 t
        const int t4 = (f & 15) * 4;
        *reinterpret_cast<float4*>(&g_xinT[(size_t)(r0 + r) * S + t0 + t4]) =
            *reinterpret_cast<const float4*>(&ot[r * XT + t4]);
    }
}

// ---------------------------------------------------------------------------
// Kernel 2: persistent scan. 8 rows x 8 cols per thread (short reduction),
//           R11 sync: 2 converged pollers + named-barrier parking.
//   Warp w: rows rowgrp*8..+7 (rowgrp = w>>3), cols 256*(w&7) + 8*lane .. +7.
//   Group A = warps with (warp&4)==0 consume cols < 1024 (produced by CTA 0..63).
// ---------------------------------------------------------------------------
__global__ void __launch_bounds__(NT, 1)
scan_kernel(const float* __restrict__ W) {
    __shared__ float cross[RPC][9];      // [row][colrange], pad 9 (9r mod 32 distinct)

    const int tid  = threadIdx.x;
    const int warp = tid >> 5;
    const int lane = tid & 31;
    const int bid  = blockIdx.x;
    const int row  = RPC * bid + warp;   // this warp's OUTPUT row (for store/xin)
    const int rowgrp = warp >> 3;        // 0: rows 0-7, 1: rows 8-15 (compute)
    const int cbase  = 256 * (warp & 7) + 8 * lane;   // this thread's 8 h cols

    // W registers: 8 rows x 8 cols (two float4 per row), coalesced load
    float4 wA[8], wB[8];
#pragma unroll
    for (int j = 0; j < 8; j++) {
        const float* wr = W + (size_t)(RPC * bid + rowgrp * 8 + j) * R + cbase;
        wA[j] = *reinterpret_cast<const float4*>(wr);
        wB[j] = *reinterpret_cast<const float4*>(wr + 4);
    }

    // xin chunks: lane l holds xinT[row][tc+l]
    const float* xrow = g_xinT + (size_t)row * S;
    float xcur = xrow[lane];             // chunk t = 0..31
    float xnxt = xrow[32 + lane];        // chunk t = 32..63

    float hprev = 0.f;                   // lane0 of warp w: h_prev of its row
    float4 hA = make_float4(0.f, 0.f, 0.f, 0.f);
    float4 hB = make_float4(0.f, 0.f, 0.f, 0.f);

    for (int t = 0; t < S; t++) {
        if ((t & 31) == 0 && t) {
            xcur = xnxt;
            const int nb = t + 32;
            if (nb < S) xnxt = xrow[nb + lane];   // 32-step prefetch distance
        }
        const float xval = __shfl_sync(0xffffffffu, xcur, t & 31);

        // ---- partial dots: 8 rows x this thread's 8 h columns (scalar FFMA) ----
        float p[8];
#pragma unroll
        for (int j = 0; j < 8; j++)
            p[j] = wA[j].x * hA.x + wA[j].y * hA.y + wA[j].z * hA.z + wA[j].w * hA.w
                 + wB[j].x * hB.x + wB[j].y * hB.y + wB[j].z * hB.z + wB[j].w * hB.w;

        // ---- in-warp butterfly: 8 values -> 1 per lane-group ----
#pragma unroll
        for (int i = 0; i < 4; i++) {
            float sv = (lane & 16) ? p[i] : p[i + 4];
            float rv = __shfl_xor_sync(0xffffffffu, sv, 16);
            p[i] = ((lane & 16) ? p[i + 4] : p[i]) + rv;
        }
#pragma unroll
        for (int i = 0; i < 2; i++) {
            float sv = (lane & 8) ? p[i] : p[i + 2];
            float rv = __shfl_xor_sync(0xffffffffu, sv, 8);
            p[i] = ((lane & 8) ? p[i + 2] : p[i]) + rv;
        }
        {
            float sv = (lane & 4) ? p[0] : p[1];
            float rv = __shfl_xor_sync(0xffffffffu, sv, 4);
            p[0] = ((lane & 4) ? p[1] : p[0]) + rv;
        }
        p[0] += __shfl_xor_sync(0xffffffffu, p[0], 2);
        p[0] += __shfl_xor_sync(0xffffffffu, p[0], 1);
        // rowloc: mask16 stage -> weight 4, mask8 -> 2, mask4 -> 1
        const int rowloc = ((lane >> 4) & 1) * 4 + ((lane >> 3) & 1) * 2 +
                           ((lane >> 2) & 1);
        if ((lane & 3) == 0) cross[rowgrp * 8 + rowloc][warp & 7] = p[0];
        __syncthreads();

        // ---- cross-warp: warp w reduces its row over the 8 col-ranges ----
        float v = (lane < 8) ? cross[warp][lane] : 0.f;
        v += __shfl_xor_sync(0xffffffffu, v, 4);
        v += __shfl_xor_sync(0xffffffffu, v, 2);
        v += __shfl_xor_sync(0xffffffffu, v, 1);

        if (lane == 0) {
            const float u = v + xval;
            const float a = fabsf(u);
            const float e = __expf(-2.f * a);
            float th = __fdividef(1.f - e, 1.f + e);     // tanh(|u|)
            th = copysignf(th, u);
            const float hn = 0.5f * hprev + 0.5f * th;   // ALPHA = 0.5
            hprev = hn;
            g_states[(size_t)t * R + row] = hn;
        }
        if (t + 1 == S) break;

        __syncthreads();   // all 16 rows stored (and cross reads done) before release

        // ---- publish: bump this CTA's half counter ----
        if (tid == 0)
            asm volatile("red.release.gpu.add.u32 [%0], %1;"
                         :: "l"(&g_cnt[bid >= NBH]), "r"(1u) : "memory");

        // ---- observe: warp0 polls half A (cols<1024), warp4 polls half B ----
        if (warp == 0 || warp == 4) {
            const unsigned* cp = &g_cnt[warp >> 2];
            const unsigned target = (unsigned)NBH * (unsigned)(t + 1);
            unsigned vv;
            do {
                asm volatile("ld.acquire.gpu.u32 %0, [%1];"
                             : "=r"(vv) : "l"(cp) : "memory");
            } while (vv < target);
        }
        // park per consumption half: group A = (warp&4)==0, group B = rest
        if ((warp & 4) == 0)
            asm volatile("bar.sync 1, 256;" ::: "memory");
        else
            asm volatile("bar.sync 2, 256;" ::: "memory");

        // ---- load own 8 h values (fresh cache lines -> coherent, L2 hit) ----
        hA = *reinterpret_cast<const float4*>(&g_states[(size_t)t * R + cbase]);
        hB = *reinterpret_cast<const float4*>(&g_states[(size_t)t * R + cbase + 4]);
    }
}

// ---------------------------------------------------------------------------
// Kernel 3: out[t][o] = states[t,:] . W_comb[o,:] + b_comb[o]
// ---------------------------------------------------------------------------
#define OT 128
#define KC 64
__global__ void __launch_bounds__(OT)
out_kernel(float* __restrict__ out) {
    __shared__ float st_s[OT][KC + 1];                  // 33.3 KB
    __shared__ unsigned long long wcs[KC][O / 2];       // 12.8 KB
    const int tid = threadIdx.x;
    const int t0  = blockIdx.x * OT;

    unsigned long long acc[O / 2];
#pragma unroll
    for (int op = 0; op < O / 2; op++) acc[op] = 0ull;

    for (int kc = 0; kc < R; kc += KC) {
        __syncthreads();
#pragma unroll
        for (int i = 0; i < (OT * KC) / (4 * OT); i++) {
            const int f  = tid + OT * i;
            const int tt = f >> 4;
            const int k4 = (f & 15) * 4;
            const float4 vv = *reinterpret_cast<const float4*>(
                &g_states[(size_t)(t0 + tt) * R + kc + k4]);
            st_s[tt][k4 + 0] = vv.x; st_s[tt][k4 + 1] = vv.y;
            st_s[tt][k4 + 2] = vv.z; st_s[tt][k4 + 3] = vv.w;
        }
        for (int i = tid; i < KC * (O / 2); i += OT) {
            const int r = i / (O / 2), op = i - r * (O / 2);
            wcs[r][op] = *reinterpret_cast<const unsigned long long*>(
                &g_wcombT[(size_t)(kc + r) * O + 2 * op]);
        }
        __syncthreads();
#pragma unroll 4
        for (int kk = 0; kk < KC; kk++) {
            const float s = st_s[tid][kk];
            const unsigned long long ss = pack2(s, s);
#pragma unroll
            for (int op = 0; op < O / 2; op++) ffma2(acc[op], wcs[kk][op], ss);
        }
    }
#pragma unroll
    for (int op = 0; op < O / 2; op++) {
        out[(size_t)(t0 + tid) * O + 2 * op + 0] = f2lo(acc[op]) + g_bcomb[2 * op + 0];
        out[(size_t)(t0 + tid) * O + 2 * op + 1] = f2hi(acc[op]) + g_bcomb[2 * op + 1];
    }
}

// ---------------------------------------------------------------------------
extern "C" void kernel_launch(void* const* d_in, const int* in_sizes, int n_in,
                              void* d_out, int out_size) {
    const float* x     = (const float*)d_in[0];
    const float* Win   = (const float*)d_in[1];
    const float* W     = (const float*)d_in[2];
    const float* fc1_w = (const float*)d_in[3];
    const float* fc1_b = (const float*)d_in[4];
    const float* fc2_w = (const float*)d_in[5];
    const float* fc2_b = (const float*)d_in[6];
    float* out = (float*)d_out;

    wcomb_kernel<<<dim3(O, 8), 256>>>(fc1_w, fc1_b, fc2_w, fc2_b);  // resets g_cnt
    xin_kernel<<<dim3(S / XT, R / XR), 256>>>(x, Win);
    scan_kernel<<<NB, NT>>>(W);
    out_kernel<<<S / OT, OT>>>(out);
}